// round 1
// baseline (speedup 1.0000x reference)
#include <cuda_runtime.h>
#include <math.h>

// Problem constants
#define D_MODEL 2048
#define N_HEADS 16
#define HEAD_D  128
#define BATCH   2
#define SEQ     2048
#define M_TOT   (BATCH * SEQ)   // 4096
#define QKV_N   (3 * D_MODEL)   // 6144

// Scratch (allocation-free: __device__ globals)
__device__ float g_qkv[(size_t)M_TOT * QKV_N];   // [4096, 6144]
__device__ float g_att[(size_t)M_TOT * D_MODEL]; // [4096, 2048]

// ---------------------------------------------------------------------------
// SGEMM: C = A @ B.  A [M,K] row-major, B [K,N] row-major, C [M,N] row-major.
// Block tile 128x128, K-tile 16, 256 threads, 8x8 register micro-tile.
// M,N,K assumed multiples of 128/128/16 (true for all calls here).
// ---------------------------------------------------------------------------
__global__ __launch_bounds__(256) void sgemm128(const float* __restrict__ A,
                                                const float* __restrict__ Bm,
                                                float* __restrict__ C,
                                                int M, int N, int K) {
    __shared__ float As[16 * 132];  // [k][m], padded stride 132
    __shared__ float Bs[16 * 128];  // [k][n]

    const int tid = threadIdx.x;
    const int tx = tid & 15;
    const int ty = tid >> 4;
    const int row0 = blockIdx.y * 128;
    const int col0 = blockIdx.x * 128;

    float acc[8][8];
#pragma unroll
    for (int i = 0; i < 8; i++)
#pragma unroll
        for (int j = 0; j < 8; j++) acc[i][j] = 0.f;

    for (int kt = 0; kt < K; kt += 16) {
        // Load A tile 128x16 -> As transposed [k][m]
#pragma unroll
        for (int i = 0; i < 2; i++) {
            int idx = tid + 256 * i;       // 0..511 float4s
            int r = idx >> 2;              // 0..127
            int c4 = idx & 3;              // 0..3
            float4 v = *(const float4*)(A + (size_t)(row0 + r) * K + kt + c4 * 4);
            As[(c4 * 4 + 0) * 132 + r] = v.x;
            As[(c4 * 4 + 1) * 132 + r] = v.y;
            As[(c4 * 4 + 2) * 132 + r] = v.z;
            As[(c4 * 4 + 3) * 132 + r] = v.w;
        }
        // Load B tile 16x128 -> Bs [k][n]
#pragma unroll
        for (int i = 0; i < 2; i++) {
            int idx = tid + 256 * i;       // 0..511 float4s
            int r = idx >> 5;              // 0..15
            int c4 = idx & 31;             // 0..31
            *(float4*)(&Bs[r * 128 + c4 * 4]) =
                *(const float4*)(Bm + (size_t)(kt + r) * N + col0 + c4 * 4);
        }
        __syncthreads();

#pragma unroll
        for (int k = 0; k < 16; k++) {
            float a[8], b[8];
            *(float4*)(a)     = *(const float4*)(&As[k * 132 + ty * 8]);
            *(float4*)(a + 4) = *(const float4*)(&As[k * 132 + ty * 8 + 4]);
            *(float4*)(b)     = *(const float4*)(&Bs[k * 128 + tx * 8]);
            *(float4*)(b + 4) = *(const float4*)(&Bs[k * 128 + tx * 8 + 4]);
#pragma unroll
            for (int i = 0; i < 8; i++)
#pragma unroll
                for (int j = 0; j < 8; j++) acc[i][j] += a[i] * b[j];
        }
        __syncthreads();
    }

#pragma unroll
    for (int i = 0; i < 8; i++) {
        float* cp = C + (size_t)(row0 + ty * 8 + i) * N + col0 + tx * 8;
        *(float4*)(cp)     = make_float4(acc[i][0], acc[i][1], acc[i][2], acc[i][3]);
        *(float4*)(cp + 4) = make_float4(acc[i][4], acc[i][5], acc[i][6], acc[i][7]);
    }
}

// ---------------------------------------------------------------------------
// Flash attention (fp32, causal). One block = 64 q-rows of one (b,h).
// qkv layout: row (b*SEQ+s), 6144 cols = [comp(3)][head(16)][hd(128)].
// Output o: [b, s, h*128 + hd]  (i.e. [B,S,D] with heads re-interleaved).
// 256 threads as 16x16 (tx, ty): scores micro-tile 4x4, O micro-tile 4x8.
// ---------------------------------------------------------------------------
#define QS_STRIDE 133
#define PS_STRIDE 68

__global__ __launch_bounds__(256) void attn_kernel(const float* __restrict__ qkv,
                                                   float* __restrict__ o) {
    extern __shared__ float sm[];
    float* Qs = sm;                      // [64][133]
    float* Ks = Qs + 64 * QS_STRIDE;     // [64][133]
    float* Vs = Ks + 64 * QS_STRIDE;     // [64][128]
    float* Ps = Vs + 64 * 128;           // [64][68]

    const int tid = threadIdx.x;
    const int tx = tid & 15;
    const int ty = tid >> 4;
    const int bh = blockIdx.x;
    const int b  = bh >> 4;
    const int h  = bh & 15;
    const int qt = (int)gridDim.y - 1 - (int)blockIdx.y;  // heavy tiles first
    const int q0 = qt * 64;
    const float scale = 0.088388347648318447f;  // 1/sqrt(128)

    const float* qb = qkv + (size_t)b * SEQ * QKV_N + h * HEAD_D;
    const float* kb = qb + D_MODEL;
    const float* vb = qb + 2 * D_MODEL;

    // Load Q tile [64][128]
#pragma unroll
    for (int i = 0; i < 8; i++) {
        int idx = tid + 256 * i;   // 2048 float4s
        int r = idx >> 5;          // 0..63
        int c4 = idx & 31;         // 0..31
        float4 v = *(const float4*)(qb + (size_t)(q0 + r) * QKV_N + c4 * 4);
        float* dst = Qs + r * QS_STRIDE + c4 * 4;
        dst[0] = v.x; dst[1] = v.y; dst[2] = v.z; dst[3] = v.w;
    }

    float m[4], l[4], O[4][8];
#pragma unroll
    for (int i = 0; i < 4; i++) {
        m[i] = -3.0e38f; l[i] = 0.f;
#pragma unroll
        for (int n = 0; n < 8; n++) O[i][n] = 0.f;
    }

    for (int kt = 0; kt <= qt; kt++) {
        const int k0 = kt * 64;
        // Load K (padded) and V (row-major) tiles
#pragma unroll
        for (int i = 0; i < 8; i++) {
            int idx = tid + 256 * i;
            int r = idx >> 5;
            int c4 = idx & 31;
            float4 kv = *(const float4*)(kb + (size_t)(k0 + r) * QKV_N + c4 * 4);
            float* kd = Ks + r * QS_STRIDE + c4 * 4;
            kd[0] = kv.x; kd[1] = kv.y; kd[2] = kv.z; kd[3] = kv.w;
            float4 vv = *(const float4*)(vb + (size_t)(k0 + r) * QKV_N + c4 * 4);
            *(float4*)(Vs + r * 128 + c4 * 4) = vv;
        }
        __syncthreads();

        // S = Q @ K^T  (64x64x128), 4x4 per thread
        float s[4][4];
#pragma unroll
        for (int i = 0; i < 4; i++)
#pragma unroll
            for (int j = 0; j < 4; j++) s[i][j] = 0.f;

        const float* qrow = Qs + (4 * ty) * QS_STRIDE;
        const float* krow = Ks + (4 * tx) * QS_STRIDE;
#pragma unroll 4
        for (int d = 0; d < 128; d++) {
            float a0 = qrow[d];
            float a1 = qrow[QS_STRIDE + d];
            float a2 = qrow[2 * QS_STRIDE + d];
            float a3 = qrow[3 * QS_STRIDE + d];
            float b0 = krow[d];
            float b1 = krow[QS_STRIDE + d];
            float b2 = krow[2 * QS_STRIDE + d];
            float b3 = krow[3 * QS_STRIDE + d];
            s[0][0] += a0 * b0; s[0][1] += a0 * b1; s[0][2] += a0 * b2; s[0][3] += a0 * b3;
            s[1][0] += a1 * b0; s[1][1] += a1 * b1; s[1][2] += a1 * b2; s[1][3] += a1 * b3;
            s[2][0] += a2 * b0; s[2][1] += a2 * b1; s[2][2] += a2 * b2; s[2][3] += a2 * b3;
            s[3][0] += a3 * b0; s[3][1] += a3 * b1; s[3][2] += a3 * b2; s[3][3] += a3 * b3;
        }

        // Online softmax (per row, reduce across the 16 tx lanes)
#pragma unroll
        for (int i = 0; i < 4; i++) {
            const int qi = q0 + 4 * ty + i;
            float rmax = -3.0e38f;
#pragma unroll
            for (int j = 0; j < 4; j++) {
                float sv = s[i][j] * scale;
                int kj = k0 + 4 * tx + j;
                if (kj > qi) sv = -1.0e9f;   // match reference mask value
                s[i][j] = sv;
                rmax = fmaxf(rmax, sv);
            }
#pragma unroll
            for (int off = 8; off >= 1; off >>= 1)
                rmax = fmaxf(rmax, __shfl_xor_sync(0xffffffffu, rmax, off));
            float mn = fmaxf(m[i], rmax);
            float alpha = __expf(m[i] - mn);
            m[i] = mn;
            float p0 = __expf(s[i][0] - mn);
            float p1 = __expf(s[i][1] - mn);
            float p2 = __expf(s[i][2] - mn);
            float p3 = __expf(s[i][3] - mn);
            float ls = p0 + p1 + p2 + p3;
#pragma unroll
            for (int off = 8; off >= 1; off >>= 1)
                ls += __shfl_xor_sync(0xffffffffu, ls, off);
            l[i] = l[i] * alpha + ls;
#pragma unroll
            for (int n = 0; n < 8; n++) O[i][n] *= alpha;
            float* pd = Ps + (4 * ty + i) * PS_STRIDE + 4 * tx;
            pd[0] = p0; pd[1] = p1; pd[2] = p2; pd[3] = p3;
        }
        __syncthreads();

        // O += P @ V  (64x128x64), 4x8 per thread
#pragma unroll 2
        for (int j = 0; j < 64; j++) {
            float a0 = Ps[(4 * ty + 0) * PS_STRIDE + j];
            float a1 = Ps[(4 * ty + 1) * PS_STRIDE + j];
            float a2 = Ps[(4 * ty + 2) * PS_STRIDE + j];
            float a3 = Ps[(4 * ty + 3) * PS_STRIDE + j];
            float4 v0 = *(const float4*)(Vs + j * 128 + 8 * tx);
            float4 v1 = *(const float4*)(Vs + j * 128 + 8 * tx + 4);
            float bv[8] = {v0.x, v0.y, v0.z, v0.w, v1.x, v1.y, v1.z, v1.w};
#pragma unroll
            for (int n = 0; n < 8; n++) {
                O[0][n] += a0 * bv[n];
                O[1][n] += a1 * bv[n];
                O[2][n] += a2 * bv[n];
                O[3][n] += a3 * bv[n];
            }
        }
        __syncthreads();
    }

    // Normalize + write: o[b, s, h*128 + n]
#pragma unroll
    for (int i = 0; i < 4; i++) {
        float inv = 1.0f / l[i];
        float* dst = o + (size_t)(b * SEQ + q0 + 4 * ty + i) * D_MODEL + h * HEAD_D + 8 * tx;
        *(float4*)(dst)     = make_float4(O[i][0] * inv, O[i][1] * inv, O[i][2] * inv, O[i][3] * inv);
        *(float4*)(dst + 4) = make_float4(O[i][4] * inv, O[i][5] * inv, O[i][6] * inv, O[i][7] * inv);
    }
}

// ---------------------------------------------------------------------------
extern "C" void kernel_launch(void* const* d_in, const int* in_sizes, int n_in,
                              void* d_out, int out_size) {
    const float* x    = (const float*)d_in[0];   // [2, 2048, 2048]
    const float* Wqkv = (const float*)d_in[1];   // [2048, 6144]
    const float* Wo   = (const float*)d_in[2];   // [2048, 2048]
    float* out = (float*)d_out;                  // [2, 2048, 2048]

    float* qkv_p = nullptr;
    float* att_p = nullptr;
    cudaGetSymbolAddress((void**)&qkv_p, g_qkv);
    cudaGetSymbolAddress((void**)&att_p, g_att);

    dim3 blk(256);

    // 1) QKV projection: [4096,2048] @ [2048,6144]
    sgemm128<<<dim3(QKV_N / 128, M_TOT / 128), blk>>>(x, Wqkv, qkv_p, M_TOT, QKV_N, D_MODEL);

    // 2) Causal flash attention
    size_t smem = (size_t)(64 * QS_STRIDE * 2 + 64 * 128 + 64 * PS_STRIDE) * sizeof(float);
    cudaFuncSetAttribute(attn_kernel, cudaFuncAttributeMaxDynamicSharedMemorySize, (int)smem);
    attn_kernel<<<dim3(BATCH * N_HEADS, SEQ / 64), blk, smem>>>(qkv_p, att_p);

    // 3) Output projection: [4096,2048] @ [2048,2048]
    sgemm128<<<dim3(D_MODEL / 128, M_TOT / 128), blk>>>(att_p, Wo, out, M_TOT, D_MODEL, D_MODEL);
}

// round 2
// speedup vs baseline: 2.9397x; 2.9397x over previous
#include <cuda_runtime.h>
#include <math.h>
#include <stdint.h>

// Problem constants
#define D_MODEL 2048
#define N_HEADS 16
#define HEAD_D  128
#define BATCH   2
#define SEQ     2048
#define M_TOT   (BATCH * SEQ)   // 4096
#define QKV_N   (3 * D_MODEL)   // 6144

// Scratch (allocation-free: __device__ globals)
__device__ float g_qkv[(size_t)M_TOT * QKV_N];   // [4096, 6144]
__device__ float g_att[(size_t)M_TOT * D_MODEL]; // [4096, 2048]

// ---------------------------------------------------------------------------
// tf32 helpers
// ---------------------------------------------------------------------------
__device__ __forceinline__ uint32_t f2tf(float f) {
    uint32_t u;
    asm("cvt.rna.tf32.f32 %0, %1;" : "=r"(u) : "f"(f));
    return u;
}

__device__ __forceinline__ void mma_tf32(float d[4], const uint32_t a[4],
                                         const uint32_t b[2]) {
    asm volatile(
        "mma.sync.aligned.m16n8k8.row.col.f32.tf32.tf32.f32 "
        "{%0,%1,%2,%3}, {%4,%5,%6,%7}, {%8,%9}, {%0,%1,%2,%3};"
        : "+f"(d[0]), "+f"(d[1]), "+f"(d[2]), "+f"(d[3])
        : "r"(a[0]), "r"(a[1]), "r"(a[2]), "r"(a[3]),
          "r"(b[0]), "r"(b[1]));
}

// ---------------------------------------------------------------------------
// tf32 GEMM: C = A @ B.  A [M,K] rm, B [K,N] rm, C [M,N] rm.
// Block 128x128, ktile 32, 256 threads = 8 warps (2x4), warp tile 64x32.
// As smem [m][k] stride 36, Bs [k][n] stride 136 (all frag LDS conflict-free).
// ---------------------------------------------------------------------------
#define GAS 36
#define GBS 136

__global__ __launch_bounds__(256, 2) void sgemm_tf32(const float* __restrict__ A,
                                                     const float* __restrict__ Bm,
                                                     float* __restrict__ C,
                                                     int M, int N, int K) {
    __shared__ uint32_t As[128 * GAS];  // 18 KB
    __shared__ uint32_t Bs[32 * GBS];   // 17.4 KB

    const int tid  = threadIdx.x;
    const int lane = tid & 31;
    const int warp = tid >> 5;
    const int g    = lane >> 2;  // group 0..7
    const int tg   = lane & 3;   // thread-in-group 0..3
    const int wm   = warp >> 2;  // 0..1
    const int wn   = warp & 3;   // 0..3
    const int row0 = blockIdx.y * 128;
    const int col0 = blockIdx.x * 128;

    float acc[4][4][4];
#pragma unroll
    for (int i = 0; i < 4; i++)
#pragma unroll
        for (int j = 0; j < 4; j++)
#pragma unroll
            for (int r = 0; r < 4; r++) acc[i][j][r] = 0.f;

    for (int kt = 0; kt < K; kt += 32) {
        // Stage A 128x32 -> As[m][k]
#pragma unroll
        for (int i = 0; i < 4; i++) {
            int idx = tid + 256 * i;   // 0..1023
            int r = idx >> 3;          // 0..127
            int c4 = idx & 7;          // 0..7
            float4 v = *(const float4*)(A + (size_t)(row0 + r) * K + kt + 4 * c4);
            uint4 t = make_uint4(f2tf(v.x), f2tf(v.y), f2tf(v.z), f2tf(v.w));
            *(uint4*)&As[r * GAS + 4 * c4] = t;
        }
        // Stage B 32x128 -> Bs[k][n]
#pragma unroll
        for (int i = 0; i < 4; i++) {
            int idx = tid + 256 * i;
            int r = idx >> 5;          // 0..31
            int c4 = idx & 31;         // 0..31
            float4 v = *(const float4*)(Bm + (size_t)(kt + r) * N + col0 + 4 * c4);
            uint4 t = make_uint4(f2tf(v.x), f2tf(v.y), f2tf(v.z), f2tf(v.w));
            *(uint4*)&Bs[r * GBS + 4 * c4] = t;
        }
        __syncthreads();

#pragma unroll
        for (int kk = 0; kk < 4; kk++) {
            const int k0 = kk * 8;
            uint32_t a[4][4], b[4][2];
#pragma unroll
            for (int mi = 0; mi < 4; mi++) {
                int rb = wm * 64 + mi * 16 + g;
                a[mi][0] = As[rb * GAS + k0 + tg];
                a[mi][1] = As[(rb + 8) * GAS + k0 + tg];
                a[mi][2] = As[rb * GAS + k0 + tg + 4];
                a[mi][3] = As[(rb + 8) * GAS + k0 + tg + 4];
            }
#pragma unroll
            for (int nj = 0; nj < 4; nj++) {
                int cb = wn * 32 + nj * 8 + g;
                b[nj][0] = Bs[(k0 + tg) * GBS + cb];
                b[nj][1] = Bs[(k0 + tg + 4) * GBS + cb];
            }
#pragma unroll
            for (int mi = 0; mi < 4; mi++)
#pragma unroll
                for (int nj = 0; nj < 4; nj++) mma_tf32(acc[mi][nj], a[mi], b[nj]);
        }
        __syncthreads();
    }

#pragma unroll
    for (int mi = 0; mi < 4; mi++)
#pragma unroll
        for (int nj = 0; nj < 4; nj++) {
            int r = row0 + wm * 64 + mi * 16 + g;
            int c = col0 + wn * 32 + nj * 8 + 2 * tg;
            *(float2*)(C + (size_t)r * N + c) = make_float2(acc[mi][nj][0], acc[mi][nj][1]);
            *(float2*)(C + (size_t)(r + 8) * N + c) = make_float2(acc[mi][nj][2], acc[mi][nj][3]);
        }
}

// ---------------------------------------------------------------------------
// Flash attention (tf32 MMA, causal). Block = 64 q-rows of one (b,h).
// 8 warps: QK score warp tile 16x32 (wq=warp>>1 rows, wk=warp&1 cols),
// PV warp tile 16x64 (same wq rows, wv=warp&1 cols).
// ---------------------------------------------------------------------------
#define QS 132
#define KS 132
#define VS 136
#define PS 72

__global__ __launch_bounds__(256) void attn_tf32(const float* __restrict__ qkv,
                                                 float* __restrict__ o) {
    extern __shared__ uint32_t smu[];
    uint32_t* Qs = smu;                   // [64][132]
    uint32_t* Ks = Qs + 64 * QS;          // [64][132]
    uint32_t* Vs = Ks + 64 * KS;          // [64][136] (k x n)
    uint32_t* Ps = Vs + 64 * VS;          // [64][72]
    float* redm = (float*)(Ps + 64 * PS); // [2][64]
    float* reds = redm + 128;             // [2][64]

    const int tid  = threadIdx.x;
    const int lane = tid & 31;
    const int warp = tid >> 5;
    const int g    = lane >> 2;
    const int tg   = lane & 3;
    const int wq   = warp >> 1;   // 0..3
    const int wk   = warp & 1;    // 0..1

    const int bh = blockIdx.x;
    const int b  = bh >> 4;
    const int h  = bh & 15;
    const int qt = (int)gridDim.y - 1 - (int)blockIdx.y;  // heavy tiles first
    const int q0 = qt * 64;
    const float scale = 0.08838834764831845f;  // 1/sqrt(128)

    const float* qb = qkv + (size_t)b * SEQ * QKV_N + h * HEAD_D;
    const float* kb = qb + D_MODEL;
    const float* vb = qb + 2 * D_MODEL;

    // Load Q tile [64][128] -> tf32
#pragma unroll
    for (int i = 0; i < 8; i++) {
        int idx = tid + 256 * i;
        int r = idx >> 5;
        int c4 = idx & 31;
        float4 v = *(const float4*)(qb + (size_t)(q0 + r) * QKV_N + 4 * c4);
        *(uint4*)&Qs[r * QS + 4 * c4] = make_uint4(f2tf(v.x), f2tf(v.y), f2tf(v.z), f2tf(v.w));
    }

    const int rowl = wq * 16 + g;       // local row (first half)
    const int rowg = q0 + rowl;         // global q row

    float m0 = -3.0e38f, m1 = -3.0e38f, l0 = 0.f, l1 = 0.f;
    float oacc[8][4];
#pragma unroll
    for (int nj = 0; nj < 8; nj++)
#pragma unroll
        for (int c = 0; c < 4; c++) oacc[nj][c] = 0.f;

    for (int kt = 0; kt <= qt; kt++) {
        const int k0 = kt * 64;
        // Stage K and V tiles
#pragma unroll
        for (int i = 0; i < 8; i++) {
            int idx = tid + 256 * i;
            int r = idx >> 5;
            int c4 = idx & 31;
            float4 kv = *(const float4*)(kb + (size_t)(k0 + r) * QKV_N + 4 * c4);
            *(uint4*)&Ks[r * KS + 4 * c4] = make_uint4(f2tf(kv.x), f2tf(kv.y), f2tf(kv.z), f2tf(kv.w));
            float4 vv = *(const float4*)(vb + (size_t)(k0 + r) * QKV_N + 4 * c4);
            *(uint4*)&Vs[r * VS + 4 * c4] = make_uint4(f2tf(vv.x), f2tf(vv.y), f2tf(vv.z), f2tf(vv.w));
        }
        __syncthreads();

        // S = Q @ K^T : warp tile 16x32
        float s[4][4];
#pragma unroll
        for (int nj = 0; nj < 4; nj++)
#pragma unroll
            for (int c = 0; c < 4; c++) s[nj][c] = 0.f;

#pragma unroll
        for (int kk = 0; kk < 16; kk++) {
            const int k8 = kk * 8;
            uint32_t a[4], bfr[4][2];
            a[0] = Qs[rowl * QS + k8 + tg];
            a[1] = Qs[(rowl + 8) * QS + k8 + tg];
            a[2] = Qs[rowl * QS + k8 + tg + 4];
            a[3] = Qs[(rowl + 8) * QS + k8 + tg + 4];
#pragma unroll
            for (int nj = 0; nj < 4; nj++) {
                int nb = wk * 32 + nj * 8 + g;
                bfr[nj][0] = Ks[nb * KS + k8 + tg];
                bfr[nj][1] = Ks[nb * KS + k8 + tg + 4];
            }
#pragma unroll
            for (int nj = 0; nj < 4; nj++) mma_tf32(s[nj], a, bfr[nj]);
        }

        // scale + causal mask + row max
        const bool diag = (kt == qt);
        float pm0 = -3.0e38f, pm1 = -3.0e38f;
#pragma unroll
        for (int nj = 0; nj < 4; nj++) {
            int c = k0 + wk * 32 + nj * 8 + 2 * tg;
            float v0 = s[nj][0] * scale;
            float v1 = s[nj][1] * scale;
            float v2 = s[nj][2] * scale;
            float v3 = s[nj][3] * scale;
            if (diag) {
                if (c > rowg) v0 = -1.0e9f;
                if (c + 1 > rowg) v1 = -1.0e9f;
                if (c > rowg + 8) v2 = -1.0e9f;
                if (c + 1 > rowg + 8) v3 = -1.0e9f;
            }
            s[nj][0] = v0; s[nj][1] = v1; s[nj][2] = v2; s[nj][3] = v3;
            pm0 = fmaxf(pm0, fmaxf(v0, v1));
            pm1 = fmaxf(pm1, fmaxf(v2, v3));
        }
        pm0 = fmaxf(pm0, __shfl_xor_sync(0xffffffffu, pm0, 1));
        pm0 = fmaxf(pm0, __shfl_xor_sync(0xffffffffu, pm0, 2));
        pm1 = fmaxf(pm1, __shfl_xor_sync(0xffffffffu, pm1, 1));
        pm1 = fmaxf(pm1, __shfl_xor_sync(0xffffffffu, pm1, 2));
        if (tg == 0) {
            redm[wk * 64 + rowl] = pm0;
            redm[wk * 64 + rowl + 8] = pm1;
        }
        __syncthreads();

        float mn0 = fmaxf(m0, fmaxf(redm[rowl], redm[64 + rowl]));
        float mn1 = fmaxf(m1, fmaxf(redm[rowl + 8], redm[64 + rowl + 8]));
        float alpha0 = __expf(m0 - mn0);
        float alpha1 = __expf(m1 - mn1);
        m0 = mn0; m1 = mn1;

        // p = exp(s - m), write P fragment, partial row sums
        float ps0 = 0.f, ps1 = 0.f;
#pragma unroll
        for (int nj = 0; nj < 4; nj++) {
            float p0 = __expf(s[nj][0] - mn0);
            float p1 = __expf(s[nj][1] - mn0);
            float p2 = __expf(s[nj][2] - mn1);
            float p3 = __expf(s[nj][3] - mn1);
            ps0 += p0 + p1;
            ps1 += p2 + p3;
            int cc = wk * 32 + nj * 8 + 2 * tg;
            *(uint2*)&Ps[rowl * PS + cc] = make_uint2(f2tf(p0), f2tf(p1));
            *(uint2*)&Ps[(rowl + 8) * PS + cc] = make_uint2(f2tf(p2), f2tf(p3));
        }
        ps0 += __shfl_xor_sync(0xffffffffu, ps0, 1);
        ps0 += __shfl_xor_sync(0xffffffffu, ps0, 2);
        ps1 += __shfl_xor_sync(0xffffffffu, ps1, 1);
        ps1 += __shfl_xor_sync(0xffffffffu, ps1, 2);
        if (tg == 0) {
            reds[wk * 64 + rowl] = ps0;
            reds[wk * 64 + rowl + 8] = ps1;
        }

        // rescale O accumulators
#pragma unroll
        for (int nj = 0; nj < 8; nj++) {
            oacc[nj][0] *= alpha0; oacc[nj][1] *= alpha0;
            oacc[nj][2] *= alpha1; oacc[nj][3] *= alpha1;
        }
        __syncthreads();

        l0 = l0 * alpha0 + reds[rowl] + reds[64 + rowl];
        l1 = l1 * alpha1 + reds[rowl + 8] + reds[64 + rowl + 8];

        // O += P @ V : warp tile 16x64 (wv = wk)
#pragma unroll
        for (int kk = 0; kk < 8; kk++) {
            const int k8 = kk * 8;
            uint32_t a[4], bfr[8][2];
            a[0] = Ps[rowl * PS + k8 + tg];
            a[1] = Ps[(rowl + 8) * PS + k8 + tg];
            a[2] = Ps[rowl * PS + k8 + tg + 4];
            a[3] = Ps[(rowl + 8) * PS + k8 + tg + 4];
#pragma unroll
            for (int nj = 0; nj < 8; nj++) {
                int nb = wk * 64 + nj * 8 + g;
                bfr[nj][0] = Vs[(k8 + tg) * VS + nb];
                bfr[nj][1] = Vs[(k8 + tg + 4) * VS + nb];
            }
#pragma unroll
            for (int nj = 0; nj < 8; nj++) mma_tf32(oacc[nj], a, bfr[nj]);
        }
        __syncthreads();
    }

    // Normalize + write to o[b, s, h*128 + d]
    float inv0 = 1.0f / l0;
    float inv1 = 1.0f / l1;
#pragma unroll
    for (int nj = 0; nj < 8; nj++) {
        int col = h * HEAD_D + wk * 64 + nj * 8 + 2 * tg;
        float* d0 = o + (size_t)(b * SEQ + rowg) * D_MODEL + col;
        float* d1 = o + (size_t)(b * SEQ + rowg + 8) * D_MODEL + col;
        *(float2*)d0 = make_float2(oacc[nj][0] * inv0, oacc[nj][1] * inv0);
        *(float2*)d1 = make_float2(oacc[nj][2] * inv1, oacc[nj][3] * inv1);
    }
}

// ---------------------------------------------------------------------------
extern "C" void kernel_launch(void* const* d_in, const int* in_sizes, int n_in,
                              void* d_out, int out_size) {
    const float* x    = (const float*)d_in[0];   // [2, 2048, 2048]
    const float* Wqkv = (const float*)d_in[1];   // [2048, 6144]
    const float* Wo   = (const float*)d_in[2];   // [2048, 2048]
    float* out = (float*)d_out;                  // [2, 2048, 2048]

    float* qkv_p = nullptr;
    float* att_p = nullptr;
    cudaGetSymbolAddress((void**)&qkv_p, g_qkv);
    cudaGetSymbolAddress((void**)&att_p, g_att);

    dim3 blk(256);

    // 1) QKV projection: [4096,2048] @ [2048,6144]
    sgemm_tf32<<<dim3(QKV_N / 128, M_TOT / 128), blk>>>(x, Wqkv, qkv_p, M_TOT, QKV_N, D_MODEL);

    // 2) Causal flash attention (tf32 MMA)
    size_t smem = (size_t)(64 * QS + 64 * KS + 64 * VS + 64 * PS) * sizeof(uint32_t)
                + 256 * sizeof(float);
    cudaFuncSetAttribute(attn_tf32, cudaFuncAttributeMaxDynamicSharedMemorySize, (int)smem);
    attn_tf32<<<dim3(BATCH * N_HEADS, SEQ / 64), blk, smem>>>(qkv_p, att_p);

    // 3) Output projection: [4096,2048] @ [2048,2048]
    sgemm_tf32<<<dim3(D_MODEL / 128, M_TOT / 128), blk>>>(att_p, Wo, out, M_TOT, D_MODEL, D_MODEL);
}

// round 4
// speedup vs baseline: 3.6455x; 1.2401x over previous
#include <cuda_runtime.h>
#include <math.h>
#include <stdint.h>

// Problem constants
#define D_MODEL 2048
#define N_HEADS 16
#define HEAD_D  128
#define BATCH   2
#define SEQ     2048
#define M_TOT   (BATCH * SEQ)   // 4096
#define QKV_N   (3 * D_MODEL)   // 6144

// Scratch (allocation-free: __device__ globals)
__device__ float g_qkv[(size_t)M_TOT * QKV_N];   // [4096, 6144]
__device__ float g_att[(size_t)M_TOT * D_MODEL]; // [4096, 2048]
__device__ float g_xr[(size_t)M_TOT * D_MODEL];  // tf32-rounded x
__device__ float g_wqkv[(size_t)D_MODEL * QKV_N];
__device__ float g_wo[(size_t)D_MODEL * D_MODEL];

// ---------------------------------------------------------------------------
// helpers
// ---------------------------------------------------------------------------
__device__ __forceinline__ uint32_t f2tf(float f) {
    uint32_t u;
    asm("cvt.rna.tf32.f32 %0, %1;" : "=r"(u) : "f"(f));
    return u;
}

__device__ __forceinline__ uint32_t smem_u32(const void* p) {
    uint32_t a;
    asm("{ .reg .u64 t; cvta.to.shared.u64 t, %1; cvt.u32.u64 %0, t; }"
        : "=r"(a) : "l"(p));
    return a;
}

__device__ __forceinline__ void mma_tf32(float d[4], const uint32_t a[4],
                                         const uint32_t b[2]) {
    asm volatile(
        "mma.sync.aligned.m16n8k8.row.col.f32.tf32.tf32.f32 "
        "{%0,%1,%2,%3}, {%4,%5,%6,%7}, {%8,%9}, {%0,%1,%2,%3};"
        : "+f"(d[0]), "+f"(d[1]), "+f"(d[2]), "+f"(d[3])
        : "r"(a[0]), "r"(a[1]), "r"(a[2]), "r"(a[3]),
          "r"(b[0]), "r"(b[1]));
}

#define CP_ASYNC16(dst, src) \
    asm volatile("cp.async.cg.shared.global [%0], [%1], 16;" :: "r"(dst), "l"(src))
#define CP_COMMIT() asm volatile("cp.async.commit_group;" ::: "memory")
#define CP_WAIT1()  asm volatile("cp.async.wait_group 1;" ::: "memory")

// ---------------------------------------------------------------------------
// tf32 pre-round kernel (elementwise, float4)
// ---------------------------------------------------------------------------
__global__ void round_tf32(const float4* __restrict__ src, float4* __restrict__ dst,
                           int n4) {
    int i = blockIdx.x * blockDim.x + threadIdx.x;
    if (i < n4) {
        float4 v = src[i];
        float4 o;
        o.x = __uint_as_float(f2tf(v.x));
        o.y = __uint_as_float(f2tf(v.y));
        o.z = __uint_as_float(f2tf(v.z));
        o.w = __uint_as_float(f2tf(v.w));
        dst[i] = o;
    }
}

// ---------------------------------------------------------------------------
// tf32 GEMM, cp.async 3-stage pipeline: C = A @ B.
// A [M,K] rm (pre-rounded tf32), B [K,N] rm (pre-rounded), C [M,N] rm.
// Block 128x128, ktile 32, 256 threads = 8 warps (2x4), warp tile 64x32.
// A smem: 128B rows, XOR-16B swizzle keyed on (m&7). Fragment banks:
//   4*((chunk)^(g)) + tg -> 32 distinct, conflict-free.
// B smem: [k][n] padded stride 136 floats. Fragment banks 8*tg + g + n0,
//   conflict-free.
// ---------------------------------------------------------------------------
#define ASZ   16384          // 128 rows * 128 B
#define BROW  544            // 136 floats * 4 B
#define BSZ   (32 * BROW)    // 17408
#define STAGE_SZ (ASZ + BSZ) // 33792
#define GEMM_SMEM (3 * STAGE_SZ)  // 101376

__global__ __launch_bounds__(256, 2) void gemm_tc(const float* __restrict__ A,
                                                  const float* __restrict__ Bm,
                                                  float* __restrict__ C,
                                                  int M, int N, int K) {
    extern __shared__ char sm[];
    const uint32_t sbase = smem_u32(sm);

    const int tid  = threadIdx.x;
    const int lane = tid & 31;
    const int warp = tid >> 5;
    const int g    = lane >> 2;  // 0..7
    const int tg   = lane & 3;   // 0..3
    const int wm   = warp >> 2;  // 0..1
    const int wn   = warp & 3;   // 0..3
    const int row0 = blockIdx.y * 128;
    const int col0 = blockIdx.x * 128;
    const int NT   = K >> 5;

    float acc[4][4][4];
#pragma unroll
    for (int i = 0; i < 4; i++)
#pragma unroll
        for (int j = 0; j < 4; j++)
#pragma unroll
            for (int r = 0; r < 4; r++) acc[i][j][r] = 0.f;

    // cp.async staging of ktile kt into buffer s
    auto stage_cp = [&](int kt, int s) {
        const uint32_t as = sbase + s * STAGE_SZ;
        const uint32_t bs = as + ASZ;
        const float* Ag = A + (size_t)row0 * K + kt * 32;
#pragma unroll
        for (int i = 0; i < 4; i++) {
            int idx = tid + 256 * i;      // 0..1023
            int m  = idx >> 3;            // 0..127
            int c4 = idx & 7;             // 0..7
            uint32_t dst = as + m * 128 + (((c4) << 4) ^ ((m & 7) << 4));
            CP_ASYNC16(dst, Ag + (size_t)m * K + 4 * c4);
        }
        const float* Bg = Bm + (size_t)(kt * 32) * N + col0;
#pragma unroll
        for (int i = 0; i < 4; i++) {
            int idx = tid + 256 * i;      // 0..1023
            int r  = idx >> 5;            // 0..31
            int c4 = idx & 31;            // 0..31
            uint32_t dst = bs + r * BROW + (c4 << 4);
            CP_ASYNC16(dst, Bg + (size_t)r * N + 4 * c4);
        }
    };

    stage_cp(0, 0); CP_COMMIT();
    if (NT > 1) stage_cp(1, 1);
    CP_COMMIT();

    int s = 0, s2 = 2 % 3;
    for (int kt = 0; kt < NT; kt++) {
        CP_WAIT1();
        __syncthreads();
        if (kt + 2 < NT) stage_cp(kt + 2, s2);
        CP_COMMIT();

        const char* as = sm + s * STAGE_SZ;
        const char* bs = as + ASZ;
#pragma unroll
        for (int kk = 0; kk < 4; kk++) {
            const int k0 = 8 * kk;
            const int ch0 = k0 >> 2;      // chunk of first 4 k's
            uint32_t a[4][4], b[4][2];
#pragma unroll
            for (int mi = 0; mi < 4; mi++) {
                int m1 = wm * 64 + mi * 16 + g;
                int m2 = m1 + 8;
                const char* r1 = as + m1 * 128;
                const char* r2 = as + m2 * 128;
                int x1 = (m1 & 7) << 4;
                int x2 = (m2 & 7) << 4;
                a[mi][0] = *(const uint32_t*)(r1 + (((ch0) << 4) ^ x1) + 4 * tg);
                a[mi][1] = *(const uint32_t*)(r2 + (((ch0) << 4) ^ x2) + 4 * tg);
                a[mi][2] = *(const uint32_t*)(r1 + (((ch0 + 1) << 4) ^ x1) + 4 * tg);
                a[mi][3] = *(const uint32_t*)(r2 + (((ch0 + 1) << 4) ^ x2) + 4 * tg);
            }
#pragma unroll
            for (int nj = 0; nj < 4; nj++) {
                int cb = wn * 32 + nj * 8 + g;
                b[nj][0] = *(const uint32_t*)(bs + (k0 + tg) * BROW + 4 * cb);
                b[nj][1] = *(const uint32_t*)(bs + (k0 + tg + 4) * BROW + 4 * cb);
            }
#pragma unroll
            for (int mi = 0; mi < 4; mi++)
#pragma unroll
                for (int nj = 0; nj < 4; nj++) mma_tf32(acc[mi][nj], a[mi], b[nj]);
        }
        __syncthreads();
        s = (s + 1) % 3;
        s2 = (s2 + 1) % 3;
    }

#pragma unroll
    for (int mi = 0; mi < 4; mi++)
#pragma unroll
        for (int nj = 0; nj < 4; nj++) {
            int r = row0 + wm * 64 + mi * 16 + g;
            int c = col0 + wn * 32 + nj * 8 + 2 * tg;
            *(float2*)(C + (size_t)r * N + c) = make_float2(acc[mi][nj][0], acc[mi][nj][1]);
            *(float2*)(C + (size_t)(r + 8) * N + c) = make_float2(acc[mi][nj][2], acc[mi][nj][3]);
        }
}

// ---------------------------------------------------------------------------
// Flash attention (tf32 mma.sync, causal). Block = 64 q-rows of one (b,h).
// Epilogue stores tf32-rounded values so out-proj can consume them raw.
// ---------------------------------------------------------------------------
#define QS 132
#define KS 132
#define VS 136
#define PS 72

__global__ __launch_bounds__(256) void attn_tf32(const float* __restrict__ qkv,
                                                 float* __restrict__ o) {
    extern __shared__ uint32_t smu[];
    uint32_t* Qs = smu;                   // [64][132]
    uint32_t* Ks = Qs + 64 * QS;          // [64][132]
    uint32_t* Vs = Ks + 64 * KS;          // [64][136] (k x n)
    uint32_t* Ps = Vs + 64 * VS;          // [64][72]
    float* redm = (float*)(Ps + 64 * PS); // [2][64]
    float* reds = redm + 128;             // [2][64]

    const int tid  = threadIdx.x;
    const int lane = tid & 31;
    const int warp = tid >> 5;
    const int g    = lane >> 2;
    const int tg   = lane & 3;
    const int wq   = warp >> 1;   // 0..3
    const int wk   = warp & 1;    // 0..1

    const int bh = blockIdx.x;
    const int b  = bh >> 4;
    const int h  = bh & 15;
    const int qt = (int)gridDim.y - 1 - (int)blockIdx.y;  // heavy tiles first
    const int q0 = qt * 64;
    const float scale = 0.08838834764831845f;  // 1/sqrt(128)

    const float* qb = qkv + (size_t)b * SEQ * QKV_N + h * HEAD_D;
    const float* kb = qb + D_MODEL;
    const float* vb = qb + 2 * D_MODEL;

    // Load Q tile [64][128] -> tf32
#pragma unroll
    for (int i = 0; i < 8; i++) {
        int idx = tid + 256 * i;
        int r = idx >> 5;
        int c4 = idx & 31;
        float4 v = *(const float4*)(qb + (size_t)(q0 + r) * QKV_N + 4 * c4);
        *(uint4*)&Qs[r * QS + 4 * c4] = make_uint4(f2tf(v.x), f2tf(v.y), f2tf(v.z), f2tf(v.w));
    }

    const int rowl = wq * 16 + g;       // local row (first half)
    const int rowg = q0 + rowl;         // global q row

    float m0 = -3.0e38f, m1 = -3.0e38f, l0 = 0.f, l1 = 0.f;
    float oacc[8][4];
#pragma unroll
    for (int nj = 0; nj < 8; nj++)
#pragma unroll
        for (int c = 0; c < 4; c++) oacc[nj][c] = 0.f;

    for (int kt = 0; kt <= qt; kt++) {
        const int k0 = kt * 64;
        // Stage K and V tiles
#pragma unroll
        for (int i = 0; i < 8; i++) {
            int idx = tid + 256 * i;
            int r = idx >> 5;
            int c4 = idx & 31;
            float4 kv = *(const float4*)(kb + (size_t)(k0 + r) * QKV_N + 4 * c4);
            *(uint4*)&Ks[r * KS + 4 * c4] = make_uint4(f2tf(kv.x), f2tf(kv.y), f2tf(kv.z), f2tf(kv.w));
            float4 vv = *(const float4*)(vb + (size_t)(k0 + r) * QKV_N + 4 * c4);
            *(uint4*)&Vs[r * VS + 4 * c4] = make_uint4(f2tf(vv.x), f2tf(vv.y), f2tf(vv.z), f2tf(vv.w));
        }
        __syncthreads();

        // S = Q @ K^T : warp tile 16x32
        float s[4][4];
#pragma unroll
        for (int nj = 0; nj < 4; nj++)
#pragma unroll
            for (int c = 0; c < 4; c++) s[nj][c] = 0.f;

#pragma unroll
        for (int kk = 0; kk < 16; kk++) {
            const int k8 = kk * 8;
            uint32_t a[4], bfr[4][2];
            a[0] = Qs[rowl * QS + k8 + tg];
            a[1] = Qs[(rowl + 8) * QS + k8 + tg];
            a[2] = Qs[rowl * QS + k8 + tg + 4];
            a[3] = Qs[(rowl + 8) * QS + k8 + tg + 4];
#pragma unroll
            for (int nj = 0; nj < 4; nj++) {
                int nb = wk * 32 + nj * 8 + g;
                bfr[nj][0] = Ks[nb * KS + k8 + tg];
                bfr[nj][1] = Ks[nb * KS + k8 + tg + 4];
            }
#pragma unroll
            for (int nj = 0; nj < 4; nj++) mma_tf32(s[nj], a, bfr[nj]);
        }

        // scale + causal mask + row max
        const bool diag = (kt == qt);
        float pm0 = -3.0e38f, pm1 = -3.0e38f;
#pragma unroll
        for (int nj = 0; nj < 4; nj++) {
            int c = k0 + wk * 32 + nj * 8 + 2 * tg;
            float v0 = s[nj][0] * scale;
            float v1 = s[nj][1] * scale;
            float v2 = s[nj][2] * scale;
            float v3 = s[nj][3] * scale;
            if (diag) {
                if (c > rowg) v0 = -1.0e9f;
                if (c + 1 > rowg) v1 = -1.0e9f;
                if (c > rowg + 8) v2 = -1.0e9f;
                if (c + 1 > rowg + 8) v3 = -1.0e9f;
            }
            s[nj][0] = v0; s[nj][1] = v1; s[nj][2] = v2; s[nj][3] = v3;
            pm0 = fmaxf(pm0, fmaxf(v0, v1));
            pm1 = fmaxf(pm1, fmaxf(v2, v3));
        }
        pm0 = fmaxf(pm0, __shfl_xor_sync(0xffffffffu, pm0, 1));
        pm0 = fmaxf(pm0, __shfl_xor_sync(0xffffffffu, pm0, 2));
        pm1 = fmaxf(pm1, __shfl_xor_sync(0xffffffffu, pm1, 1));
        pm1 = fmaxf(pm1, __shfl_xor_sync(0xffffffffu, pm1, 2));
        if (tg == 0) {
            redm[wk * 64 + rowl] = pm0;
            redm[wk * 64 + rowl + 8] = pm1;
        }
        __syncthreads();

        float mn0 = fmaxf(m0, fmaxf(redm[rowl], redm[64 + rowl]));
        float mn1 = fmaxf(m1, fmaxf(redm[rowl + 8], redm[64 + rowl + 8]));
        float alpha0 = __expf(m0 - mn0);
        float alpha1 = __expf(m1 - mn1);
        m0 = mn0; m1 = mn1;

        // p = exp(s - m), write P fragment, partial row sums
        float ps0 = 0.f, ps1 = 0.f;
#pragma unroll
        for (int nj = 0; nj < 4; nj++) {
            float p0 = __expf(s[nj][0] - mn0);
            float p1 = __expf(s[nj][1] - mn0);
            float p2 = __expf(s[nj][2] - mn1);
            float p3 = __expf(s[nj][3] - mn1);
            ps0 += p0 + p1;
            ps1 += p2 + p3;
            int cc = wk * 32 + nj * 8 + 2 * tg;
            *(uint2*)&Ps[rowl * PS + cc] = make_uint2(f2tf(p0), f2tf(p1));
            *(uint2*)&Ps[(rowl + 8) * PS + cc] = make_uint2(f2tf(p2), f2tf(p3));
        }
        ps0 += __shfl_xor_sync(0xffffffffu, ps0, 1);
        ps0 += __shfl_xor_sync(0xffffffffu, ps0, 2);
        ps1 += __shfl_xor_sync(0xffffffffu, ps1, 1);
        ps1 += __shfl_xor_sync(0xffffffffu, ps1, 2);
        if (tg == 0) {
            reds[wk * 64 + rowl] = ps0;
            reds[wk * 64 + rowl + 8] = ps1;
        }

        // rescale O accumulators
#pragma unroll
        for (int nj = 0; nj < 8; nj++) {
            oacc[nj][0] *= alpha0; oacc[nj][1] *= alpha0;
            oacc[nj][2] *= alpha1; oacc[nj][3] *= alpha1;
        }
        __syncthreads();

        l0 = l0 * alpha0 + reds[rowl] + reds[64 + rowl];
        l1 = l1 * alpha1 + reds[rowl + 8] + reds[64 + rowl + 8];

        // O += P @ V : warp tile 16x64
#pragma unroll
        for (int kk = 0; kk < 8; kk++) {
            const int k8 = kk * 8;
            uint32_t a[4], bfr[8][2];
            a[0] = Ps[rowl * PS + k8 + tg];
            a[1] = Ps[(rowl + 8) * PS + k8 + tg];
            a[2] = Ps[rowl * PS + k8 + tg + 4];
            a[3] = Ps[(rowl + 8) * PS + k8 + tg + 4];
#pragma unroll
            for (int nj = 0; nj < 8; nj++) {
                int nb = wk * 64 + nj * 8 + g;
                bfr[nj][0] = Vs[(k8 + tg) * VS + nb];
                bfr[nj][1] = Vs[(k8 + tg + 4) * VS + nb];
            }
#pragma unroll
            for (int nj = 0; nj < 8; nj++) mma_tf32(oacc[nj], a, bfr[nj]);
        }
        __syncthreads();
    }

    // Normalize + write tf32-rounded to o[b, s, h*128 + d]
    float inv0 = 1.0f / l0;
    float inv1 = 1.0f / l1;
#pragma unroll
    for (int nj = 0; nj < 8; nj++) {
        int col = h * HEAD_D + wk * 64 + nj * 8 + 2 * tg;
        float* d0 = o + (size_t)(b * SEQ + rowg) * D_MODEL + col;
        float* d1 = o + (size_t)(b * SEQ + rowg + 8) * D_MODEL + col;
        *(float2*)d0 = make_float2(__uint_as_float(f2tf(oacc[nj][0] * inv0)),
                                   __uint_as_float(f2tf(oacc[nj][1] * inv0)));
        *(float2*)d1 = make_float2(__uint_as_float(f2tf(oacc[nj][2] * inv1)),
                                   __uint_as_float(f2tf(oacc[nj][3] * inv1)));
    }
}

// ---------------------------------------------------------------------------
extern "C" void kernel_launch(void* const* d_in, const int* in_sizes, int n_in,
                              void* d_out, int out_size) {
    const float* x    = (const float*)d_in[0];   // [2, 2048, 2048]
    const float* Wqkv = (const float*)d_in[1];   // [2048, 6144]
    const float* Wo   = (const float*)d_in[2];   // [2048, 2048]
    float* out = (float*)d_out;                  // [2, 2048, 2048]

    float *qkv_p, *att_p, *xr_p, *wqkv_p, *wo_p;
    cudaGetSymbolAddress((void**)&qkv_p, g_qkv);
    cudaGetSymbolAddress((void**)&att_p, g_att);
    cudaGetSymbolAddress((void**)&xr_p, g_xr);
    cudaGetSymbolAddress((void**)&wqkv_p, g_wqkv);
    cudaGetSymbolAddress((void**)&wo_p, g_wo);

    cudaFuncSetAttribute(gemm_tc, cudaFuncAttributeMaxDynamicSharedMemorySize, GEMM_SMEM);
    size_t at_smem = (size_t)(64 * QS + 64 * KS + 64 * VS + 64 * PS) * sizeof(uint32_t)
                   + 256 * sizeof(float);
    cudaFuncSetAttribute(attn_tf32, cudaFuncAttributeMaxDynamicSharedMemorySize, (int)at_smem);

    dim3 blk(256);

    // 0) pre-round inputs to tf32
    {
        int n4x = M_TOT * D_MODEL / 4;
        int n4q = D_MODEL * QKV_N / 4;
        int n4o = D_MODEL * D_MODEL / 4;
        round_tf32<<<(n4x + 255) / 256, 256>>>((const float4*)x, (float4*)xr_p, n4x);
        round_tf32<<<(n4q + 255) / 256, 256>>>((const float4*)Wqkv, (float4*)wqkv_p, n4q);
        round_tf32<<<(n4o + 255) / 256, 256>>>((const float4*)Wo, (float4*)wo_p, n4o);
    }

    // 1) QKV projection: [4096,2048] @ [2048,6144]
    gemm_tc<<<dim3(QKV_N / 128, M_TOT / 128), blk, GEMM_SMEM>>>(xr_p, wqkv_p, qkv_p,
                                                                M_TOT, QKV_N, D_MODEL);

    // 2) Causal flash attention (tf32 mma.sync)
    attn_tf32<<<dim3(BATCH * N_HEADS, SEQ / 64), blk, at_smem>>>(qkv_p, att_p);

    // 3) Output projection: [4096,2048] @ [2048,2048]
    gemm_tc<<<dim3(D_MODEL / 128, M_TOT / 128), blk, GEMM_SMEM>>>(att_p, wo_p, out,
                                                                  M_TOT, D_MODEL, D_MODEL);
}